// round 14
// baseline (speedup 1.0000x reference)
#include <cuda_runtime.h>
#include <cuda_bf16.h>
#include <cstdint>

#define T_STEPS 512
#define HID 32
#define IN_SZ 8
#define CH 8                      // steps per x chunk (256 B / warp)
#define NCHUNK (T_STEPS / CH)     // 64

typedef unsigned long long u64;
typedef unsigned int u32;

__device__ __forceinline__ u64 pack2(float lo, float hi) {
    u64 r; asm("mov.b64 %0, {%1, %2};" : "=l"(r) : "f"(lo), "f"(hi)); return r;
}
__device__ __forceinline__ void unpack2(u64 v, float& lo, float& hi) {
    asm("mov.b64 {%0, %1}, %2;" : "=f"(lo), "=f"(hi) : "l"(v));
}
// Blackwell packed fp32 FMA: one FMA-pipe slot, two MACs.
__device__ __forceinline__ u64 fma2(u64 a, u64 b, u64 c) {
    u64 d; asm("fma.rn.f32x2 %0, %1, %2, %3;" : "=l"(d) : "l"(a), "l"(b), "l"(c));
    return d;
}

__device__ __forceinline__ u32 smem_u32(const void* p) {
    u32 a;
    asm("{ .reg .u64 t; cvta.to.shared.u64 t, %1; cvt.u32.u64 %0, t; }"
        : "=r"(a) : "l"(p));
    return a;
}
__device__ __forceinline__ void cp_async8(u32 dst, const void* src) {
    asm volatile("cp.async.ca.shared.global [%0], [%1], 8;" :: "r"(dst), "l"(src));
}

__device__ __forceinline__ float sigmoid_fast(float x) {
    return __fdividef(1.0f, 1.0f + __expf(-x));
}
__device__ __forceinline__ float tanh_fast(float x) {
    return __fdividef(2.0f, 1.0f + __expf(-2.0f * x)) - 1.0f;
}

__global__ __launch_bounds__(128, 2)
void lstm_warp_kernel(
    const float* __restrict__ x,     // [B, T, 8]
    const float* __restrict__ W_ih,  // [128, 8]
    const float* __restrict__ W_hh,  // [128, 32]
    const float* __restrict__ b_ih,  // [128]
    const float* __restrict__ b_hh,  // [128]
    const float* __restrict__ W_fc,  // [1, 32]
    const float* __restrict__ b_fc,  // [1]
    float* __restrict__ out,         // [B]
    int B)
{
    // x staging: per warp, double-buffered 8-step chunks (256 B each)
    __shared__ __align__(16) float xs[4][2][CH * IN_SZ];
    // h broadcast staging, double-buffered per step parity
    __shared__ __align__(8) float hbuf[4][2][HID];

    const int wib  = threadIdx.x >> 5;
    const int warp = blockIdx.x * 4 + wib;
    const int lane = threadIdx.x & 31;
    if (warp >= B) return;

    // ---- register-resident packed weights: lane j owns hidden unit j ----
    u64 whhp[4][HID / 2];
    u64 wihp[4][IN_SZ / 2];
    u64 biasp[4];
    const u64* whh64 = reinterpret_cast<const u64*>(W_hh);
    const u64* wih64 = reinterpret_cast<const u64*>(W_ih);
#pragma unroll
    for (int g = 0; g < 4; g++) {
        const int row = g * HID + lane;
        biasp[g] = pack2(b_ih[row] + b_hh[row], 0.0f);
#pragma unroll
        for (int d = 0; d < IN_SZ / 2; d++) wihp[g][d] = wih64[row * (IN_SZ / 2) + d];
#pragma unroll
        for (int k = 0; k < HID / 2; k++)  whhp[g][k] = whh64[row * (HID / 2) + k];
    }

    // per-lane global source: 8 B per lane covers one 256 B chunk per warp
    const float* xw = x + (size_t)warp * ((size_t)T_STEPS * IN_SZ);

    // ---- prologue: prefetch chunks 0 and 1 ----
    {
        u32 d0 = smem_u32(&xs[wib][0][lane * 2]);
        cp_async8(d0, xw + 0 * (CH * IN_SZ) + lane * 2);
        asm volatile("cp.async.commit_group;");
        u32 d1 = smem_u32(&xs[wib][1][lane * 2]);
        cp_async8(d1, xw + 1 * (CH * IN_SZ) + lane * 2);
        asm volatile("cp.async.commit_group;");
    }

    float h = 0.0f, c = 0.0f;
    // xacc[g]: bias + x(t)·W_ih, prepared one step AHEAD so the 16 FMA2s
    // overlap the previous step's MUFU activation tail.
    u64 xacc0, xacc1, xacc2, xacc3;
    int t = 0;

#pragma unroll 1
    for (int ck = 0; ck < NCHUNK; ck++) {
        asm volatile("cp.async.wait_group 1;");   // chunk ck has landed
        __syncwarp();
        const u64* xb = reinterpret_cast<const u64*>(xs[wib][ck & 1]);

        // boundary: prepare xacc for the first step of this chunk
        {
            xacc0 = biasp[0]; xacc1 = biasp[1]; xacc2 = biasp[2]; xacc3 = biasp[3];
#pragma unroll
            for (int d = 0; d < IN_SZ / 2; d++) {
                const u64 xv = xb[d];
                xacc0 = fma2(wihp[0][d], xv, xacc0);
                xacc1 = fma2(wihp[1][d], xv, xacc1);
                xacc2 = fma2(wihp[2][d], xv, xacc2);
                xacc3 = fma2(wihp[3][d], xv, xacc3);
            }
        }

#pragma unroll
        for (int s = 0; s < CH; s++, t++) {
            // broadcast h through smem
            float* hb = hbuf[wib][t & 1];
            hb[lane] = h;
            __syncwarp();

            // consume the pre-computed input+bias accumulators
            u64 a0 = xacc0, a1 = xacc1, a2 = xacc2, a3 = xacc3;

            // recurrence: 16 pair iterations, 4 independent FMA2 chains
            const u64* hp = reinterpret_cast<const u64*>(hb);
#pragma unroll
            for (int k = 0; k < HID / 2; k++) {
                const u64 hk = hp[k];
                a0 = fma2(whhp[0][k], hk, a0);
                a1 = fma2(whhp[1][k], hk, a1);
                a2 = fma2(whhp[2][k], hk, a2);
                a3 = fma2(whhp[3][k], hk, a3);
            }

            float i0, i1, f0, f1, g0, g1, o0, o1;
            unpack2(a0, i0, i1);
            unpack2(a1, f0, f1);
            unpack2(a2, g0, g1);
            unpack2(a3, o0, o1);

            // activations (MUFU-heavy tail) ...
            const float ig = sigmoid_fast(i0 + i1);
            const float fg = sigmoid_fast(f0 + f1);
            const float gg = tanh_fast(g0 + g1);
            const float og = sigmoid_fast(o0 + o1);

            // ... overlapped with next step's input-gate FMAs (independent of h)
            if (s < CH - 1) {
                xacc0 = biasp[0]; xacc1 = biasp[1]; xacc2 = biasp[2]; xacc3 = biasp[3];
#pragma unroll
                for (int d = 0; d < IN_SZ / 2; d++) {
                    const u64 xv = xb[(s + 1) * (IN_SZ / 2) + d];
                    xacc0 = fma2(wihp[0][d], xv, xacc0);
                    xacc1 = fma2(wihp[1][d], xv, xacc1);
                    xacc2 = fma2(wihp[2][d], xv, xacc2);
                    xacc3 = fma2(wihp[3][d], xv, xacc3);
                }
            }

            c = fmaf(fg, c, ig * gg);
            h = og * tanh_fast(c);
        }

        // prefetch chunk ck+2 into the buffer we just finished reading
        if (ck + 2 < NCHUNK) {
            u32 dst = smem_u32(&xs[wib][ck & 1][lane * 2]);
            cp_async8(dst, xw + (ck + 2) * (CH * IN_SZ) + lane * 2);
        }
        asm volatile("cp.async.commit_group;");   // commit (possibly empty) group
    }

    // ---- final FC ----
    float v = h * W_fc[lane];
#pragma unroll
    for (int off = 16; off; off >>= 1)
        v += __shfl_xor_sync(0xffffffffu, v, off);
    if (lane == 0) out[warp] = v + b_fc[0];
}

extern "C" void kernel_launch(void* const* d_in, const int* in_sizes, int n_in,
                              void* d_out, int out_size) {
    const float* x    = (const float*)d_in[0];
    const float* W_ih = (const float*)d_in[1];
    const float* W_hh = (const float*)d_in[2];
    const float* b_ih = (const float*)d_in[3];
    const float* b_hh = (const float*)d_in[4];
    const float* W_fc = (const float*)d_in[5];
    const float* b_fc = (const float*)d_in[6];
    float* out = (float*)d_out;

    const int B = in_sizes[0] / (T_STEPS * IN_SZ);   // 8192
    const int blocks = (B + 3) / 4;                  // 4 warps / block
    lstm_warp_kernel<<<blocks, 128>>>(x, W_ih, W_hh, b_ih, b_hh, W_fc, b_fc, out, B);
}

// round 16
// speedup vs baseline: 1.0621x; 1.0621x over previous
#include <cuda_runtime.h>
#include <cuda_bf16.h>
#include <cstdint>

#define T_STEPS 512
#define HID 32
#define IN_SZ 8
#define CH 8                      // steps per x chunk
#define NCHUNK (T_STEPS / CH)     // 64

typedef unsigned long long u64;
typedef unsigned int u32;

__device__ __forceinline__ u64 pack2(float lo, float hi) {
    u64 r; asm("mov.b64 %0, {%1, %2};" : "=l"(r) : "f"(lo), "f"(hi)); return r;
}
__device__ __forceinline__ void unpack2(u64 v, float& lo, float& hi) {
    asm("mov.b64 {%0, %1}, %2;" : "=f"(lo), "=f"(hi) : "l"(v));
}
// Blackwell packed fp32 FMA: one FMA-pipe slot, two MACs.
__device__ __forceinline__ u64 fma2(u64 a, u64 b, u64 c) {
    u64 d; asm("fma.rn.f32x2 %0, %1, %2, %3;" : "=l"(d) : "l"(a), "l"(b), "l"(c));
    return d;
}

__device__ __forceinline__ u32 smem_u32(const void* p) {
    u32 a;
    asm("{ .reg .u64 t; cvta.to.shared.u64 t, %1; cvt.u32.u64 %0, t; }"
        : "=r"(a) : "l"(p));
    return a;
}
__device__ __forceinline__ void cp_async16(u32 dst, const void* src) {
    asm volatile("cp.async.ca.shared.global [%0], [%1], 16;" :: "r"(dst), "l"(src));
}

__device__ __forceinline__ float sigmoid_fast(float x) {
    return __fdividef(1.0f, 1.0f + __expf(-x));
}
__device__ __forceinline__ float tanh_fast(float x) {
    return __fdividef(2.0f, 1.0f + __expf(-2.0f * x)) - 1.0f;
}

__global__ __launch_bounds__(128, 2)
void lstm_warp_kernel(
    const float* __restrict__ x,     // [B, T, 8]
    const float* __restrict__ W_ih,  // [128, 8]
    const float* __restrict__ W_hh,  // [128, 32]
    const float* __restrict__ b_ih,  // [128]
    const float* __restrict__ b_hh,  // [128]
    const float* __restrict__ W_fc,  // [1, 32]
    const float* __restrict__ b_fc,  // [1]
    float* __restrict__ out,         // [B]
    int B)
{
    // x staging: per warp, double-buffered, 2 samples x 8 steps (512 B / buffer)
    __shared__ __align__(16) float xs[4][2][2 * CH * IN_SZ];
    // h broadcast: 2 samples x 32, double-buffered per step parity
    __shared__ __align__(8) float hbuf[4][2][2 * HID];

    const int wib  = threadIdx.x >> 5;
    const int pair = blockIdx.x * 4 + wib;       // handles samples 2*pair, 2*pair+1
    const int lane = threadIdx.x & 31;
    const int npairs = B >> 1;
    if (pair >= npairs) return;

    // ---- register-resident packed weights (shared by both samples) ----
    u64 whhp[4][HID / 2];
    u64 wihp[4][IN_SZ / 2];
    u64 biasp[4];
    const u64* whh64 = reinterpret_cast<const u64*>(W_hh);
    const u64* wih64 = reinterpret_cast<const u64*>(W_ih);
#pragma unroll
    for (int g = 0; g < 4; g++) {
        const int row = g * HID + lane;
        biasp[g] = pack2(b_ih[row] + b_hh[row], 0.0f);
#pragma unroll
        for (int d = 0; d < IN_SZ / 2; d++) wihp[g][d] = wih64[row * (IN_SZ / 2) + d];
#pragma unroll
        for (int k = 0; k < HID / 2; k++)  whhp[g][k] = whh64[row * (HID / 2) + k];
    }

    // lanes 0-15 stage sample 0's chunk, lanes 16-31 sample 1's (16 B/lane)
    const int smp = lane >> 4;
    const int sof = (lane & 15) * 4;
    const float* xsrc = x + (size_t)(2 * pair + smp) * ((size_t)T_STEPS * IN_SZ) + sof;

    // ---- prologue: prefetch chunks 0 and 1 ----
    {
        u32 d0 = smem_u32(&xs[wib][0][smp * (CH * IN_SZ) + sof]);
        cp_async16(d0, xsrc);
        asm volatile("cp.async.commit_group;");
        u32 d1 = smem_u32(&xs[wib][1][smp * (CH * IN_SZ) + sof]);
        cp_async16(d1, xsrc + CH * IN_SZ);
        asm volatile("cp.async.commit_group;");
    }

    float h0 = 0.0f, c0 = 0.0f, h1 = 0.0f, c1 = 0.0f;
    u64 xA0, xA1, xA2, xA3;   // sample0: bias + x(t)·W_ih, one step ahead
    u64 xB0, xB1, xB2, xB3;   // sample1
    int t = 0;

#pragma unroll 1
    for (int ck = 0; ck < NCHUNK; ck++) {
        asm volatile("cp.async.wait_group 1;");
        __syncwarp();
        const u64* xb0 = reinterpret_cast<const u64*>(&xs[wib][ck & 1][0]);
        const u64* xb1 = xb0 + (CH * IN_SZ) / 2;

        // boundary: xacc for first step of chunk (both samples)
        xA0 = biasp[0]; xA1 = biasp[1]; xA2 = biasp[2]; xA3 = biasp[3];
        xB0 = biasp[0]; xB1 = biasp[1]; xB2 = biasp[2]; xB3 = biasp[3];
#pragma unroll
        for (int d = 0; d < IN_SZ / 2; d++) {
            const u64 xv0 = xb0[d], xv1 = xb1[d];
            xA0 = fma2(wihp[0][d], xv0, xA0);  xB0 = fma2(wihp[0][d], xv1, xB0);
            xA1 = fma2(wihp[1][d], xv0, xA1);  xB1 = fma2(wihp[1][d], xv1, xB1);
            xA2 = fma2(wihp[2][d], xv0, xA2);  xB2 = fma2(wihp[2][d], xv1, xB2);
            xA3 = fma2(wihp[3][d], xv0, xA3);  xB3 = fma2(wihp[3][d], xv1, xB3);
        }

#pragma unroll
        for (int s = 0; s < CH; s++, t++) {
            // broadcast both h values through smem
            float* hb = hbuf[wib][t & 1];
            hb[lane] = h0;
            hb[HID + lane] = h1;
            __syncwarp();

            u64 a0 = xA0, a1 = xA1, a2 = xA2, a3 = xA3;
            u64 b0 = xB0, b1 = xB1, b2 = xB2, b3 = xB3;

            // recurrence: 16 pair iterations, 8 independent FMA2 chains
            const u64* hp0 = reinterpret_cast<const u64*>(hb);
            const u64* hp1 = hp0 + HID / 2;
#pragma unroll
            for (int k = 0; k < HID / 2; k++) {
                const u64 hk0 = hp0[k], hk1 = hp1[k];
                a0 = fma2(whhp[0][k], hk0, a0);  b0 = fma2(whhp[0][k], hk1, b0);
                a1 = fma2(whhp[1][k], hk0, a1);  b1 = fma2(whhp[1][k], hk1, b1);
                a2 = fma2(whhp[2][k], hk0, a2);  b2 = fma2(whhp[2][k], hk1, b2);
                a3 = fma2(whhp[3][k], hk0, a3);  b3 = fma2(whhp[3][k], hk1, b3);
            }

            float u0, u1, v0, v1;
            // sample 0 activations
            unpack2(a0, u0, u1); const float ig0 = sigmoid_fast(u0 + u1);
            unpack2(a1, u0, u1); const float fg0 = sigmoid_fast(u0 + u1);
            unpack2(a2, u0, u1); const float gg0 = tanh_fast(u0 + u1);
            unpack2(a3, u0, u1); const float og0 = sigmoid_fast(u0 + u1);
            // sample 1 activations
            unpack2(b0, v0, v1); const float ig1 = sigmoid_fast(v0 + v1);
            unpack2(b1, v0, v1); const float fg1 = sigmoid_fast(v0 + v1);
            unpack2(b2, v0, v1); const float gg1 = tanh_fast(v0 + v1);
            unpack2(b3, v0, v1); const float og1 = sigmoid_fast(v0 + v1);

            // overlap: next step's input-gate FMAs (independent of h)
            if (s < CH - 1) {
                xA0 = biasp[0]; xA1 = biasp[1]; xA2 = biasp[2]; xA3 = biasp[3];
                xB0 = biasp[0]; xB1 = biasp[1]; xB2 = biasp[2]; xB3 = biasp[3];
#pragma unroll
                for (int d = 0; d < IN_SZ / 2; d++) {
                    const u64 xv0 = xb0[(s + 1) * (IN_SZ / 2) + d];
                    const u64 xv1 = xb1[(s + 1) * (IN_SZ / 2) + d];
                    xA0 = fma2(wihp[0][d], xv0, xA0);  xB0 = fma2(wihp[0][d], xv1, xB0);
                    xA1 = fma2(wihp[1][d], xv0, xA1);  xB1 = fma2(wihp[1][d], xv1, xB1);
                    xA2 = fma2(wihp[2][d], xv0, xA2);  xB2 = fma2(wihp[2][d], xv1, xB2);
                    xA3 = fma2(wihp[3][d], xv0, xA3);  xB3 = fma2(wihp[3][d], xv1, xB3);
                }
            }

            c0 = fmaf(fg0, c0, ig0 * gg0);  h0 = og0 * tanh_fast(c0);
            c1 = fmaf(fg1, c1, ig1 * gg1);  h1 = og1 * tanh_fast(c1);
        }

        // prefetch chunk ck+2 into the buffer just consumed
        if (ck + 2 < NCHUNK) {
            u32 dst = smem_u32(&xs[wib][ck & 1][smp * (CH * IN_SZ) + sof]);
            cp_async16(dst, xsrc + (ck + 2) * (CH * IN_SZ));
        }
        asm volatile("cp.async.commit_group;");
    }

    // ---- final FC for both samples ----
    const float wfc = W_fc[lane];
    float r0 = h0 * wfc, r1 = h1 * wfc;
#pragma unroll
    for (int off = 16; off; off >>= 1) {
        r0 += __shfl_xor_sync(0xffffffffu, r0, off);
        r1 += __shfl_xor_sync(0xffffffffu, r1, off);
    }
    if (lane == 0) {
        const float bf = b_fc[0];
        out[2 * pair]     = r0 + bf;
        out[2 * pair + 1] = r1 + bf;
    }
}

extern "C" void kernel_launch(void* const* d_in, const int* in_sizes, int n_in,
                              void* d_out, int out_size) {
    const float* x    = (const float*)d_in[0];
    const float* W_ih = (const float*)d_in[1];
    const float* W_hh = (const float*)d_in[2];
    const float* b_ih = (const float*)d_in[3];
    const float* b_hh = (const float*)d_in[4];
    const float* W_fc = (const float*)d_in[5];
    const float* b_fc = (const float*)d_in[6];
    float* out = (float*)d_out;

    const int B = in_sizes[0] / (T_STEPS * IN_SZ);   // 8192
    const int npairs = B / 2;                        // 4096 warps
    const int blocks = (npairs + 3) / 4;             // 4 warps / block
    lstm_warp_kernel<<<blocks, 128>>>(x, W_ih, W_hh, b_ih, b_hh, W_fc, b_fc, out, B);
}

// round 17
// speedup vs baseline: 1.2768x; 1.2021x over previous
#include <cuda_runtime.h>
#include <cuda_bf16.h>
#include <cstdint>

#define T_STEPS 512
#define HID 32
#define IN_SZ 8
#define CH 8                      // steps per x chunk
#define NCHUNK (T_STEPS / CH)     // 64

typedef unsigned long long u64;
typedef unsigned int u32;

__device__ __forceinline__ u64 pack2(float lo, float hi) {
    u64 r; asm("mov.b64 %0, {%1, %2};" : "=l"(r) : "f"(lo), "f"(hi)); return r;
}
__device__ __forceinline__ void unpack2(u64 v, float& lo, float& hi) {
    asm("mov.b64 {%0, %1}, %2;" : "=f"(lo), "=f"(hi) : "l"(v));
}
// Blackwell packed fp32 FMA: one FMA-pipe slot, two MACs.
__device__ __forceinline__ u64 fma2(u64 a, u64 b, u64 c) {
    u64 d; asm("fma.rn.f32x2 %0, %1, %2, %3;" : "=l"(d) : "l"(a), "l"(b), "l"(c));
    return d;
}

__device__ __forceinline__ u32 smem_u32(const void* p) {
    u32 a;
    asm("{ .reg .u64 t; cvta.to.shared.u64 t, %1; cvt.u32.u64 %0, t; }"
        : "=r"(a) : "l"(p));
    return a;
}
__device__ __forceinline__ void cp_async16(u32 dst, const void* src) {
    asm volatile("cp.async.ca.shared.global [%0], [%1], 16;" :: "r"(dst), "l"(src));
}

// Single-MUFU activations (MUFU.TANH): abs err ~6e-4, damped by the LSTM's
// forget-gate contraction -> bounded steady-state error, no T-compounding.
__device__ __forceinline__ float tanh_mufu(float x) {
    float y; asm("tanh.approx.f32 %0, %1;" : "=f"(y) : "f"(x)); return y;
}
__device__ __forceinline__ float sigmoid_mufu(float x) {
    float y; asm("tanh.approx.f32 %0, %1;" : "=f"(y) : "f"(x * 0.5f));
    return fmaf(y, 0.5f, 0.5f);
}

__global__ __launch_bounds__(128, 2)
void lstm_warp_kernel(
    const float* __restrict__ x,     // [B, T, 8]
    const float* __restrict__ W_ih,  // [128, 8]
    const float* __restrict__ W_hh,  // [128, 32]
    const float* __restrict__ b_ih,  // [128]
    const float* __restrict__ b_hh,  // [128]
    const float* __restrict__ W_fc,  // [1, 32]
    const float* __restrict__ b_fc,  // [1]
    float* __restrict__ out,         // [B]
    int B)
{
    // x staging: per warp, double-buffered, 2 samples x 8 steps (512 B / buffer)
    __shared__ __align__(16) float xs[4][2][2 * CH * IN_SZ];
    // h broadcast: 2 samples x 32, double-buffered per step parity
    __shared__ __align__(8) float hbuf[4][2][2 * HID];

    const int wib  = threadIdx.x >> 5;
    const int pair = blockIdx.x * 4 + wib;       // handles samples 2*pair, 2*pair+1
    const int lane = threadIdx.x & 31;
    const int npairs = B >> 1;
    if (pair >= npairs) return;

    // ---- register-resident packed weights (shared by both samples) ----
    u64 whhp[4][HID / 2];
    u64 wihp[4][IN_SZ / 2];
    u64 biasp[4];
    const u64* whh64 = reinterpret_cast<const u64*>(W_hh);
    const u64* wih64 = reinterpret_cast<const u64*>(W_ih);
#pragma unroll
    for (int g = 0; g < 4; g++) {
        const int row = g * HID + lane;
        biasp[g] = pack2(b_ih[row] + b_hh[row], 0.0f);
#pragma unroll
        for (int d = 0; d < IN_SZ / 2; d++) wihp[g][d] = wih64[row * (IN_SZ / 2) + d];
#pragma unroll
        for (int k = 0; k < HID / 2; k++)  whhp[g][k] = whh64[row * (HID / 2) + k];
    }

    // lanes 0-15 stage sample 0's chunk, lanes 16-31 sample 1's (16 B/lane)
    const int smp = lane >> 4;
    const int sof = (lane & 15) * 4;
    const float* xsrc = x + (size_t)(2 * pair + smp) * ((size_t)T_STEPS * IN_SZ) + sof;

    // ---- prologue: prefetch chunks 0 and 1 ----
    {
        u32 d0 = smem_u32(&xs[wib][0][smp * (CH * IN_SZ) + sof]);
        cp_async16(d0, xsrc);
        asm volatile("cp.async.commit_group;");
        u32 d1 = smem_u32(&xs[wib][1][smp * (CH * IN_SZ) + sof]);
        cp_async16(d1, xsrc + CH * IN_SZ);
        asm volatile("cp.async.commit_group;");
    }

    float h0 = 0.0f, c0 = 0.0f, h1 = 0.0f, c1 = 0.0f;
    u64 xA0, xA1, xA2, xA3;   // sample0: bias + x(t)·W_ih, one step ahead
    u64 xB0, xB1, xB2, xB3;   // sample1
    int t = 0;

#pragma unroll 1
    for (int ck = 0; ck < NCHUNK; ck++) {
        asm volatile("cp.async.wait_group 1;");
        __syncwarp();
        const u64* xb0 = reinterpret_cast<const u64*>(&xs[wib][ck & 1][0]);
        const u64* xb1 = xb0 + (CH * IN_SZ) / 2;

        // boundary: xacc for first step of chunk (both samples)
        xA0 = biasp[0]; xA1 = biasp[1]; xA2 = biasp[2]; xA3 = biasp[3];
        xB0 = biasp[0]; xB1 = biasp[1]; xB2 = biasp[2]; xB3 = biasp[3];
#pragma unroll
        for (int d = 0; d < IN_SZ / 2; d++) {
            const u64 xv0 = xb0[d], xv1 = xb1[d];
            xA0 = fma2(wihp[0][d], xv0, xA0);  xB0 = fma2(wihp[0][d], xv1, xB0);
            xA1 = fma2(wihp[1][d], xv0, xA1);  xB1 = fma2(wihp[1][d], xv1, xB1);
            xA2 = fma2(wihp[2][d], xv0, xA2);  xB2 = fma2(wihp[2][d], xv1, xB2);
            xA3 = fma2(wihp[3][d], xv0, xA3);  xB3 = fma2(wihp[3][d], xv1, xB3);
        }

#pragma unroll
        for (int s = 0; s < CH; s++, t++) {
            // broadcast both h values through smem
            float* hb = hbuf[wib][t & 1];
            hb[lane] = h0;
            hb[HID + lane] = h1;
            __syncwarp();

            u64 a0 = xA0, a1 = xA1, a2 = xA2, a3 = xA3;
            u64 b0 = xB0, b1 = xB1, b2 = xB2, b3 = xB3;

            // recurrence: 16 pair iterations, 8 independent FMA2 chains
            const u64* hp0 = reinterpret_cast<const u64*>(hb);
            const u64* hp1 = hp0 + HID / 2;
#pragma unroll
            for (int k = 0; k < HID / 2; k++) {
                const u64 hk0 = hp0[k], hk1 = hp1[k];
                a0 = fma2(whhp[0][k], hk0, a0);  b0 = fma2(whhp[0][k], hk1, b0);
                a1 = fma2(whhp[1][k], hk0, a1);  b1 = fma2(whhp[1][k], hk1, b1);
                a2 = fma2(whhp[2][k], hk0, a2);  b2 = fma2(whhp[2][k], hk1, b2);
                a3 = fma2(whhp[3][k], hk0, a3);  b3 = fma2(whhp[3][k], hk1, b3);
            }

            float u0, u1, v0, v1;
            // sample 0 activations (single-MUFU each)
            unpack2(a0, u0, u1); const float ig0 = sigmoid_mufu(u0 + u1);
            unpack2(a1, u0, u1); const float fg0 = sigmoid_mufu(u0 + u1);
            unpack2(a2, u0, u1); const float gg0 = tanh_mufu(u0 + u1);
            unpack2(a3, u0, u1); const float og0 = sigmoid_mufu(u0 + u1);
            // sample 1 activations
            unpack2(b0, v0, v1); const float ig1 = sigmoid_mufu(v0 + v1);
            unpack2(b1, v0, v1); const float fg1 = sigmoid_mufu(v0 + v1);
            unpack2(b2, v0, v1); const float gg1 = tanh_mufu(v0 + v1);
            unpack2(b3, v0, v1); const float og1 = sigmoid_mufu(v0 + v1);

            // overlap: next step's input-gate FMAs (independent of h)
            if (s < CH - 1) {
                xA0 = biasp[0]; xA1 = biasp[1]; xA2 = biasp[2]; xA3 = biasp[3];
                xB0 = biasp[0]; xB1 = biasp[1]; xB2 = biasp[2]; xB3 = biasp[3];
#pragma unroll
                for (int d = 0; d < IN_SZ / 2; d++) {
                    const u64 xv0 = xb0[(s + 1) * (IN_SZ / 2) + d];
                    const u64 xv1 = xb1[(s + 1) * (IN_SZ / 2) + d];
                    xA0 = fma2(wihp[0][d], xv0, xA0);  xB0 = fma2(wihp[0][d], xv1, xB0);
                    xA1 = fma2(wihp[1][d], xv0, xA1);  xB1 = fma2(wihp[1][d], xv1, xB1);
                    xA2 = fma2(wihp[2][d], xv0, xA2);  xB2 = fma2(wihp[2][d], xv1, xB2);
                    xA3 = fma2(wihp[3][d], xv0, xA3);  xB3 = fma2(wihp[3][d], xv1, xB3);
                }
            }

            c0 = fmaf(fg0, c0, ig0 * gg0);  h0 = og0 * tanh_mufu(c0);
            c1 = fmaf(fg1, c1, ig1 * gg1);  h1 = og1 * tanh_mufu(c1);
        }

        // prefetch chunk ck+2 into the buffer just consumed
        if (ck + 2 < NCHUNK) {
            u32 dst = smem_u32(&xs[wib][ck & 1][smp * (CH * IN_SZ) + sof]);
            cp_async16(dst, xsrc + (ck + 2) * (CH * IN_SZ));
        }
        asm volatile("cp.async.commit_group;");
    }

    // ---- final FC for both samples ----
    const float wfc = W_fc[lane];
    float r0 = h0 * wfc, r1 = h1 * wfc;
#pragma unroll
    for (int off = 16; off; off >>= 1) {
        r0 += __shfl_xor_sync(0xffffffffu, r0, off);
        r1 += __shfl_xor_sync(0xffffffffu, r1, off);
    }
    if (lane == 0) {
        const float bf = b_fc[0];
        out[2 * pair]     = r0 + bf;
        out[2 * pair + 1] = r1 + bf;
    }
}

extern "C" void kernel_launch(void* const* d_in, const int* in_sizes, int n_in,
                              void* d_out, int out_size) {
    const float* x    = (const float*)d_in[0];
    const float* W_ih = (const float*)d_in[1];
    const float* W_hh = (const float*)d_in[2];
    const float* b_ih = (const float*)d_in[3];
    const float* b_hh = (const float*)d_in[4];
    const float* W_fc = (const float*)d_in[5];
    const float* b_fc = (const float*)d_in[6];
    float* out = (float*)d_out;

    const int B = in_sizes[0] / (T_STEPS * IN_SZ);   // 8192
    const int npairs = B / 2;                        // 4096 warps
    const int blocks = (npairs + 3) / 4;             // 4 warps / block
    lstm_warp_kernel<<<blocks, 128>>>(x, W_ih, W_hh, b_ih, b_hh, W_fc, b_fc, out, B);
}